// round 16
// baseline (speedup 1.0000x reference)
#include <cuda_runtime.h>
#include <cuda_fp16.h>

#define SEQ 4096
#define HID 1024
#define NCTA 128
#define CSTRIDE 32
#define NSLOT 16
#define NREG 4           // register-resident chains per warp (rest in SMEM)
#define NCHMAX 10

// ---------------- device scratch ----------------
__device__ float  g_Zu[SEQ * HID];
__device__ float  g_Zr[SEQ * HID];
__device__ float  g_Zc[SEQ * HID];
__device__ __half g_Hh[4][SEQ * HID];      // fp16 hidden-state exchange
__device__ int    g_ctr[4][NSLOT * CSTRIDE];

__global__ void reset_ctrs_kernel() {
    int i = blockIdx.x * blockDim.x + threadIdx.x;
    if (i < 4 * NSLOT * CSTRIDE) ((int*)g_ctr)[i] = 0;
}

// ---------------- memory helpers (proven sync primitives) ----------------
__device__ __forceinline__ uint4 ldcg4u(const uint4* p) {
    uint4 v;
    asm volatile("ld.global.cg.v4.u32 {%0,%1,%2,%3},[%4];"
                 : "=r"(v.x), "=r"(v.y), "=r"(v.z), "=r"(v.w) : "l"(p) : "memory");
    return v;
}
__device__ __forceinline__ void stcg_h(__half* p, __half v) {
    unsigned short b = *(unsigned short*)&v;
    asm volatile("st.global.cg.u16 [%0],%1;" :: "l"(p), "h"(b) : "memory");
}
__device__ __forceinline__ int ldacq(const int* p) {
    int v;
    asm volatile("ld.acquire.gpu.global.s32 %0,[%1];" : "=r"(v) : "l"(p) : "memory");
    return v;
}
__device__ __forceinline__ void red_release_add(int* p, int v) {
    asm volatile("red.release.gpu.global.add.s32 [%0],%1;" :: "l"(p), "r"(v) : "memory");
}
__device__ __forceinline__ float sigf(float x) { return 1.f / (1.f + __expf(-x)); }

__device__ __forceinline__ unsigned pack_h2(float a, float b) {
    __half2 h = __floats2half2_rn(a, b);
    return *(unsigned*)&h;
}
// fp16 SIMD dot of 8 elems, fp32 result
__device__ __forceinline__ float dot4u(const uint4& wv, const uint4& hv) {
    const __half2* w = (const __half2*)&wv;
    const __half2* h = (const __half2*)&hv;
    __half2 acc = __hmul2(w[0], h[0]);
    acc = __hfma2(w[1], h[1], acc);
    acc = __hfma2(w[2], h[2], acc);
    acc = __hfma2(w[3], h[3], acc);
    float2 f = __half22float2(acc);
    return f.x + f.y;
}

// ---------------- fp32 SGEMM batch (layer-0 input projections) -------------
struct GemmJob { const float* A; const float* B; float* C; };
__global__ __launch_bounds__(256) void sgemm_nt_batch(GemmJob j0, GemmJob j1, GemmJob j2) {
    const GemmJob job = (blockIdx.z == 0) ? j0 : (blockIdx.z == 1) ? j1 : j2;
    const float* __restrict__ A = job.A;
    const float* __restrict__ B = job.B;
    float* __restrict__ C = job.C;
    const int K = HID, N = HID;
    __shared__ float As[8][128];
    __shared__ float Bs[8][128];
    const int tid = threadIdx.x;
    const int m0 = blockIdx.y * 128;
    const int n0 = blockIdx.x * 128;
    const int tx = tid & 15;
    const int ty = tid >> 4;
    const int lrow = tid >> 1;
    const int kp = (tid & 1) * 4;

    const float* Ap = A + (m0 + lrow) * K + kp;
    const float* Bp = B + (n0 + lrow) * K + kp;

    float acc[8][8];
#pragma unroll
    for (int i = 0; i < 8; i++)
#pragma unroll
        for (int j = 0; j < 8; j++) acc[i][j] = 0.f;

    for (int k0 = 0; k0 < K; k0 += 8) {
        float4 av = *(const float4*)(Ap + k0);
        float4 bv = *(const float4*)(Bp + k0);
        __syncthreads();
        As[kp + 0][lrow] = av.x; As[kp + 1][lrow] = av.y;
        As[kp + 2][lrow] = av.z; As[kp + 3][lrow] = av.w;
        Bs[kp + 0][lrow] = bv.x; Bs[kp + 1][lrow] = bv.y;
        Bs[kp + 2][lrow] = bv.z; Bs[kp + 3][lrow] = bv.w;
        __syncthreads();
#pragma unroll
        for (int kk = 0; kk < 8; kk++) {
            float a[8], b[8];
#pragma unroll
            for (int i = 0; i < 8; i++) a[i] = As[kk][ty * 8 + i];
#pragma unroll
            for (int j = 0; j < 8; j++) b[j] = Bs[kk][tx * 8 + j];
#pragma unroll
            for (int i = 0; i < 8; i++)
#pragma unroll
                for (int j = 0; j < 8; j++) acc[i][j] = fmaf(a[i], b[j], acc[i][j]);
        }
    }
#pragma unroll
    for (int i = 0; i < 8; i++) {
        float* Cp = C + (m0 + ty * 8 + i) * N + n0 + tx * 8;
#pragma unroll
        for (int j = 0; j < 8; j++) Cp[j] = acc[i][j];
    }
}

// ---------------- quad-layer fused GRU scan, vector-homogeneous warps ------
// 128 CTAs x 512 threads. Group v = warps 4v..4v+3 owns ALL chains reading
// h_v: layer-v u,r,c (24) + layer-(v+1) s,q (16) for v<3 (10 chains/warp);
// group 3: layer-3 u,r,c (6 chains/warp). All chains in a warp read the SAME
// row h_v(R-1-v): each warp polls layer-v counters itself and loads the fp16
// row straight from L2 into registers — NO SMEM h staging, NO barA.
// Weights: NREG in regs, rest in SMEM (conflict-free q*512+L*16).
// One __syncthreads per round (barB); res4 ping-pong makes it WAR-safe.
// Warp 15 (lightest) computes all 32 instance gates + st.cg + red.release.
struct QuadArgs {
    const float *Wu, *Wr, *Wc, *Bu, *Br, *Bc, *Uh, *Uhr, *Zu, *Zr, *Zc;
    __half *H;
    float *out;
    int *ctr;
};

#define WROW_BYTES (96 * 2048)
#define RES4_BYTES (2 * 160 * 4 * 4)
#define SMEM_TOTAL_Q (WROW_BYTES + RES4_BYTES)

__global__ __launch_bounds__(512, 1) void quad_scan(QuadArgs a) {
    extern __shared__ char smem[];
    char*  wrow_b = smem;
    float* res4   = (float*)(smem + WROW_BYTES);

    const int tid = threadIdx.x;
    const int w = tid >> 5, L = tid & 31;
    const int bid = blockIdx.x;
    const size_t HH = (size_t)HID * HID;

    const int v = w >> 2;                 // input-vector (= producer layer) id
    const int gw = w & 3;                 // warp index within group
    const int nch = (v < 3) ? 10 : 6;

    uint4 wreg[NREG][4];
    int meta[NCHMAX];

    // ---- init: resolve chains, convert weights to fp16 (regs / SMEM) ----
#pragma unroll
    for (int k = 0; k < NCHMAX; k++) {
        meta[k] = -1;
        if (k >= nch) continue;
        const int c = gw * nch + k;
        int l, j, kind;
        if (v < 3) {
            if (c < 24) { l = v; j = c / 3; kind = c % 3; }
            else { const int cc = c - 24; l = v + 1; j = cc >> 1; kind = 3 + (cc & 1); }
        } else { l = 3; j = c / 3; kind = c % 3; }
        const int jf = (bid << 3) + j;
        const float* wp;
        if (kind == 0)      wp = a.Wu  + (size_t)l * HH + (size_t)jf * HID;
        else if (kind == 1) wp = a.Wr  + (size_t)l * HH + (size_t)jf * HID;
        else if (kind == 2) wp = a.Wc  + (size_t)l * HH + (size_t)jf * HID;
        else if (kind == 3) wp = a.Uh  + (size_t)(l - 1) * HH + (size_t)jf * HID;
        else                wp = a.Uhr + (size_t)(l - 1) * HH + (size_t)jf * HID;
        const int roff = (l * 8 + j) * 5 + kind;
        meta[k] = l | (roff << 5);

        unsigned tmp[16];
        const float* rp = wp + 32 * L;
#pragma unroll
        for (int i = 0; i < 8; i++) {
            float4 f = __ldg((const float4*)rp + i);
            tmp[2 * i]     = pack_h2(f.x, f.y);
            tmp[2 * i + 1] = pack_h2(f.z, f.w);
        }
        if (k < NREG) {
#pragma unroll
            for (int q = 0; q < 4; q++)
                wreg[k][q] = make_uint4(tmp[4 * q], tmp[4 * q + 1],
                                        tmp[4 * q + 2], tmp[4 * q + 3]);
        } else {
            char* rb = wrow_b + (size_t)(w * 6 + (k - NREG)) * 2048;
#pragma unroll
            for (int q = 0; q < 4; q++)
                *(uint4*)(rb + q * 512 + L * 16) =
                    make_uint4(tmp[4 * q], tmp[4 * q + 1],
                               tmp[4 * q + 2], tmp[4 * q + 3]);
        }
    }

    // gate-lane state (warp 15, lane = instance: gl=L>>3, output L&7)
    const int gl = L >> 3;
    const int gj = (bid << 3) + (L & 7);
    float hj = 0.f, bu = 0.f, br = 0.f, bc = 0.f;
    if (w == 15) {
        bu = a.Bu[gl * HID + gj]; br = a.Br[gl * HID + gj]; bc = a.Bc[gl * HID + gj];
    }
    __syncthreads();

    for (int R = 0; R < SEQ + 3; R++) {
        // prefetch layer-0 gate input terms (warp 15, lanes 0-7 are gl=0)
        float zu = 0.f, zr = 0.f, zc = 0.f;
        if (w == 15 && gl == 0 && R < SEQ) {
            zu = __ldg(a.Zu + (size_t)R * HID + gj);
            zr = __ldg(a.Zr + (size_t)R * HID + gj);
            zc = __ldg(a.Zc + (size_t)R * HID + gj);
        }

        // per-warp: poll layer-v counters, load row h_v(R-1-v) -> registers
        uint4 hreg[4];
        const int rowIdx = R - 1 - v;
        const int lastR = (v < 3) ? (SEQ + v) : (SEQ + 2);
        if (rowIdx >= 0 && R <= lastR) {
            if (L < NSLOT) {
                const int* cp = a.ctr + v * (NSLOT * CSTRIDE) + L * CSTRIDE;
                const int tgt = (R - v) * 64;
                while (ldacq(cp) < tgt) { }
            }
            __syncwarp();
            const uint4* hr = (const uint4*)(a.H + ((size_t)v * SEQ + rowIdx) * HID) + L * 4;
            hreg[0] = ldcg4u(hr + 0);
            hreg[1] = ldcg4u(hr + 1);
            hreg[2] = ldcg4u(hr + 2);
            hreg[3] = ldcg4u(hr + 3);
        } else {
            const uint4 z = make_uint4(0, 0, 0, 0);
            hreg[0] = z; hreg[1] = z; hreg[2] = z; hreg[3] = z;
        }

        // chains: dot + 3-shfl partial reduce (R13-proven inline style)
        float* resR = res4 + (R & 1) * 160 * 4;
#pragma unroll
        for (int k = 0; k < NCHMAX; k++) {
            const int m = meta[k];
            if (m < 0) continue;
            const int l = m & 3;
            const int t = R - l;
            if (t < 0 || t >= SEQ) continue;
            float s = 0.f;
#pragma unroll
            for (int q = 0; q < 4; q++) {
                uint4 wg;
                if (k < NREG) wg = wreg[k][q];
                else wg = *(const uint4*)(wrow_b + (size_t)(w * 6 + (k - NREG)) * 2048 + q * 512 + L * 16);
                s += dot4u(wg, hreg[q]);
            }
            s += __shfl_xor_sync(0xffffffffu, s, 16);
            s += __shfl_xor_sync(0xffffffffu, s, 8);
            s += __shfl_xor_sync(0xffffffffu, s, 4);
            if (L < 4) resR[(m >> 5) * 4 + L] = s;
        }
        __syncthreads();   // barB: res4(R) complete; prior gates done

        // gates: warp 15, lane = instance
        if (w == 15) {
            const int t = R - gl;
            if (t >= 0 && t < SEQ) {
                const int ibase = (gl * 8 + (L & 7)) * 5;
                const float4 p0 = *(const float4*)(resR + (ibase + 0) * 4);
                const float4 p1 = *(const float4*)(resR + (ibase + 1) * 4);
                const float4 p2 = *(const float4*)(resR + (ibase + 2) * 4);
                const float r0 = (p0.x + p0.y) + (p0.z + p0.w);
                const float r1 = (p1.x + p1.y) + (p1.z + p1.w);
                const float r2 = (p2.x + p2.y) + (p2.z + p2.w);
                float u, r, c;
                if (gl == 0) {
                    u = sigf(r0 + zu + bu);
                    r = sigf(r1 + zr + br);
                    c = sigf(zc + r * r2 + bc);
                } else {
                    const float4 p3 = *(const float4*)(resR + (ibase + 3) * 4);
                    const float4 p4 = *(const float4*)(resR + (ibase + 4) * 4);
                    const float s5 = (p3.x + p3.y) + (p3.z + p3.w);
                    const float q5 = (p4.x + p4.y) + (p4.z + p4.w);
                    u = sigf(s5 + r0 + bu);       // shared Uh term feeds u...
                    r = sigf(q5 + r1 + br);
                    c = sigf(s5 + r * r2 + bc);   // ...and c (aliased parameter)
                }
                hj = fmaf(u, hj - c, c);
                stcg_h(a.H + ((size_t)gl * SEQ + t) * HID + gj, __float2half_rn(hj));
                red_release_add(a.ctr + gl * (NSLOT * CSTRIDE) + (bid & (NSLOT - 1)) * CSTRIDE, 1);
                if (t == SEQ - 1) a.out[gl * HID + gj] = hj;
            }
        }
    }
}

// ---------------- launch ----------------
extern "C" void kernel_launch(void* const* d_in, const int* in_sizes, int n_in,
                              void* d_out, int out_size) {
    const float* x   = (const float*)d_in[0];
    const float* Uu  = (const float*)d_in[1];
    const float* Ur  = (const float*)d_in[2];
    const float* U   = (const float*)d_in[3];
    const float* Wu  = (const float*)d_in[4];
    const float* Wr  = (const float*)d_in[5];
    const float* W   = (const float*)d_in[6];
    const float* Bu  = (const float*)d_in[7];
    const float* Br  = (const float*)d_in[8];
    const float* B   = (const float*)d_in[9];
    const float* Uhr = (const float*)d_in[10];
    const float* Uh  = (const float*)d_in[11];
    float* out = (float*)d_out;

    float *Zu, *Zr, *Zc;
    __half* Hh;
    int* ct;
    cudaGetSymbolAddress((void**)&Zu, g_Zu);
    cudaGetSymbolAddress((void**)&Zr, g_Zr);
    cudaGetSymbolAddress((void**)&Zc, g_Zc);
    cudaGetSymbolAddress((void**)&Hh, g_Hh);
    cudaGetSymbolAddress((void**)&ct, g_ctr);

    cudaFuncSetAttribute(quad_scan, cudaFuncAttributeMaxDynamicSharedMemorySize,
                         SMEM_TOTAL_Q);

    reset_ctrs_kernel<<<(4 * NSLOT * CSTRIDE + 255) / 256, 256>>>();

    {   // layer 0 input projections
        dim3 gg(HID / 128, SEQ / 128, 3);
        GemmJob A0{x, Uu, Zu}, B0{x, Ur, Zr}, C0{x, U, Zc};
        sgemm_nt_batch<<<gg, 256>>>(A0, B0, C0);
    }

    QuadArgs q;
    q.Wu = Wu; q.Wr = Wr; q.Wc = W;
    q.Bu = Bu; q.Br = Br; q.Bc = B;
    q.Uh = Uh; q.Uhr = Uhr;
    q.Zu = Zu; q.Zr = Zr; q.Zc = Zc;
    q.H = Hh; q.out = out; q.ctr = ct;
    quad_scan<<<NCTA, 512, SMEM_TOTAL_Q>>>(q);

    (void)in_sizes; (void)n_in; (void)out_size;
}

// round 17
// speedup vs baseline: 1.3961x; 1.3961x over previous
#include <cuda_runtime.h>
#include <cuda_fp16.h>

#define SEQ 4096
#define HID 1024
#define NCTA 128
#define CSTRIDE 32
#define NSLOT 16
#define NREG 4           // register-resident chains per warp (rest in SMEM)
#define NCHMAX 11

// ---------------- device scratch ----------------
__device__ float  g_Zu[SEQ * HID];
__device__ float  g_Zr[SEQ * HID];
__device__ float  g_Zc[SEQ * HID];
__device__ __half g_Hh[4][SEQ * HID];      // fp16 hidden-state exchange
__device__ int    g_ctr[4][NSLOT * CSTRIDE];

__global__ void reset_ctrs_kernel() {
    int i = blockIdx.x * blockDim.x + threadIdx.x;
    if (i < 4 * NSLOT * CSTRIDE) ((int*)g_ctr)[i] = 0;
}

// ---------------- memory helpers (proven sync primitives) ----------------
__device__ __forceinline__ uint4 ldcg4u(const uint4* p) {
    uint4 v;
    asm volatile("ld.global.cg.v4.u32 {%0,%1,%2,%3},[%4];"
                 : "=r"(v.x), "=r"(v.y), "=r"(v.z), "=r"(v.w) : "l"(p) : "memory");
    return v;
}
__device__ __forceinline__ void stcg_h(__half* p, __half v) {
    unsigned short b = *(unsigned short*)&v;
    asm volatile("st.global.cg.u16 [%0],%1;" :: "l"(p), "h"(b) : "memory");
}
__device__ __forceinline__ int ldacq(const int* p) {
    int v;
    asm volatile("ld.acquire.gpu.global.s32 %0,[%1];" : "=r"(v) : "l"(p) : "memory");
    return v;
}
__device__ __forceinline__ void red_release_add(int* p, int v) {
    asm volatile("red.release.gpu.global.add.s32 [%0],%1;" :: "l"(p), "r"(v) : "memory");
}
__device__ __forceinline__ float sigf(float x) { return 1.f / (1.f + __expf(-x)); }

__device__ __forceinline__ unsigned pack_h2(float a, float b) {
    __half2 h = __floats2half2_rn(a, b);
    return *(unsigned*)&h;
}
// fp16 SIMD dot of 8 elems, fp32 result
__device__ __forceinline__ float dot4u(const uint4& wv, const uint4& hv) {
    const __half2* w = (const __half2*)&wv;
    const __half2* h = (const __half2*)&hv;
    __half2 acc = __hmul2(w[0], h[0]);
    acc = __hfma2(w[1], h[1], acc);
    acc = __hfma2(w[2], h[2], acc);
    acc = __hfma2(w[3], h[3], acc);
    float2 f = __half22float2(acc);
    return f.x + f.y;
}

// ---------------- fp32 SGEMM batch (layer-0 input projections) -------------
struct GemmJob { const float* A; const float* B; float* C; };
__global__ __launch_bounds__(256) void sgemm_nt_batch(GemmJob j0, GemmJob j1, GemmJob j2) {
    const GemmJob job = (blockIdx.z == 0) ? j0 : (blockIdx.z == 1) ? j1 : j2;
    const float* __restrict__ A = job.A;
    const float* __restrict__ B = job.B;
    float* __restrict__ C = job.C;
    const int K = HID, N = HID;
    __shared__ float As[8][128];
    __shared__ float Bs[8][128];
    const int tid = threadIdx.x;
    const int m0 = blockIdx.y * 128;
    const int n0 = blockIdx.x * 128;
    const int tx = tid & 15;
    const int ty = tid >> 4;
    const int lrow = tid >> 1;
    const int kp = (tid & 1) * 4;

    const float* Ap = A + (m0 + lrow) * K + kp;
    const float* Bp = B + (n0 + lrow) * K + kp;

    float acc[8][8];
#pragma unroll
    for (int i = 0; i < 8; i++)
#pragma unroll
        for (int j = 0; j < 8; j++) acc[i][j] = 0.f;

    for (int k0 = 0; k0 < K; k0 += 8) {
        float4 av = *(const float4*)(Ap + k0);
        float4 bv = *(const float4*)(Bp + k0);
        __syncthreads();
        As[kp + 0][lrow] = av.x; As[kp + 1][lrow] = av.y;
        As[kp + 2][lrow] = av.z; As[kp + 3][lrow] = av.w;
        Bs[kp + 0][lrow] = bv.x; Bs[kp + 1][lrow] = bv.y;
        Bs[kp + 2][lrow] = bv.z; Bs[kp + 3][lrow] = bv.w;
        __syncthreads();
#pragma unroll
        for (int kk = 0; kk < 8; kk++) {
            float a[8], b[8];
#pragma unroll
            for (int i = 0; i < 8; i++) a[i] = As[kk][ty * 8 + i];
#pragma unroll
            for (int j = 0; j < 8; j++) b[j] = Bs[kk][tx * 8 + j];
#pragma unroll
            for (int i = 0; i < 8; i++)
#pragma unroll
                for (int j = 0; j < 8; j++) acc[i][j] = fmaf(a[i], b[j], acc[i][j]);
        }
    }
#pragma unroll
    for (int i = 0; i < 8; i++) {
        float* Cp = C + (m0 + ty * 8 + i) * N + n0 + tx * 8;
#pragma unroll
        for (int j = 0; j < 8; j++) Cp[j] = acc[i][j];
    }
}

// ---------------- quad-layer fused GRU scan (R13 + load rebalance) ---------
// 128 CTAs x 512 threads (16 warps). Chain map: staging warps 0-3 take the
// FIRST 3 chains of their own vector group (v=w) -> all data in hreg, zero
// hbuf reads; warps 4-15 take 11 chains each (4 reg rows + 7 SMEM rows).
// Round R: layer l does t=R-l. Warps 0-3 poll + RAW-copy fp16 h rows into
// SMEM (and keep them in regs); barA; chains (dot + 3-shfl reduce -> res4);
// barB; warp 15 lane=instance gates + fp16 st.cg + red.release. Sync,
// barriers, layouts byte-identical to R13.
struct QuadArgs {
    const float *Wu, *Wr, *Wc, *Bu, *Br, *Bc, *Uh, *Uhr, *Zu, *Zr, *Zc;
    __half *H;
    float *out;
    int *ctr;
};

#define WROW_BYTES (84 * 2048)
#define HBUF_BYTES (4 * 2048)
#define RES4_BYTES (160 * 4 * 4)
#define SMEM_TOTAL_Q (WROW_BYTES + HBUF_BYTES + RES4_BYTES)

__global__ __launch_bounds__(512, 1) void quad_scan(QuadArgs a) {
    extern __shared__ char smem[];
    char*  wrow_b = smem;
    char*  hbuf_b = smem + WROW_BYTES;
    float* res4   = (float*)(smem + WROW_BYTES + HBUF_BYTES);

    const int tid = threadIdx.x;
    const int w = tid >> 5, L = tid & 31;
    const int bid = blockIdx.x;
    const size_t HH = (size_t)HID * HID;

    const int nch = (w < 4) ? 3 : 11;

    uint4 wreg[NREG][4];
    int meta[NCHMAX];
    int vMaj;

    // ---- chain id for (w, k) ----
    // staging warps: c = 40*w + k (first 3 of own group; group 3 base 120)
    // compute warps: g = (w-4)*11 + k over remaining 132, mapped past the
    //   reserved first-3 of each group: v0 rem [3,40), v1 [43,80),
    //   v2 [83,120), v3 [123,144)
    // ---- init: resolve chains, convert weights to fp16 (regs / SMEM) ----
    {
        int vMid = -1;
#pragma unroll
        for (int k = 0; k < NCHMAX; k++) {
            meta[k] = -1;
            if (k >= nch) continue;
            int c;
            if (w < 4) c = 40 * w + k;           // group-3 base is 120 = 40*3 ✓
            else {
                const int g = (w - 4) * 11 + k;
                if (g < 37)       c = 3 + g;
                else if (g < 74)  c = 43 + (g - 37);
                else if (g < 111) c = 83 + (g - 74);
                else              c = 123 + (g - 111);
            }
            const int v = (c < 40) ? 0 : (c < 80) ? 1 : (c < 120) ? 2 : 3;
            if (k == nch / 2) vMid = v;
            const int gg = c - 40 * v;
            int l, j, kind;
            if (v == 3 || gg < 24) { l = v; j = gg / 3; kind = gg - 3 * j; }
            else { const int g2 = gg - 24; l = v + 1; j = g2 >> 1; kind = 3 + (g2 & 1); }
            const int jf = (bid << 3) + j;
            const float* wp;
            if (kind == 0)      wp = a.Wu  + (size_t)l * HH + (size_t)jf * HID;
            else if (kind == 1) wp = a.Wr  + (size_t)l * HH + (size_t)jf * HID;
            else if (kind == 2) wp = a.Wc  + (size_t)l * HH + (size_t)jf * HID;
            else if (kind == 3) wp = a.Uh  + (size_t)(l - 1) * HH + (size_t)jf * HID;
            else                wp = a.Uhr + (size_t)(l - 1) * HH + (size_t)jf * HID;
            const int roff = (l * 8 + j) * 5 + kind;
            meta[k] = l | (v << 3) | (roff << 5);

            unsigned tmp[16];
            const float* rp = wp + 32 * L;
#pragma unroll
            for (int i = 0; i < 8; i++) {
                float4 f = __ldg((const float4*)rp + i);
                tmp[2 * i]     = pack_h2(f.x, f.y);
                tmp[2 * i + 1] = pack_h2(f.z, f.w);
            }
            if (k < NREG) {
#pragma unroll
                for (int q = 0; q < 4; q++)
                    wreg[k][q] = make_uint4(tmp[4 * q], tmp[4 * q + 1],
                                            tmp[4 * q + 2], tmp[4 * q + 3]);
            } else {
                char* rb = wrow_b + (size_t)((w - 4) * 7 + (k - NREG)) * 2048;
#pragma unroll
                for (int q = 0; q < 4; q++)
                    *(uint4*)(rb + q * 512 + L * 16) =
                        make_uint4(tmp[4 * q], tmp[4 * q + 1],
                                   tmp[4 * q + 2], tmp[4 * q + 3]);
            }
        }
        vMaj = (w < 4) ? w : vMid;
    }

    // gate-lane state (warp 15, lane = instance: gl=L>>3, output L&7)
    const int gl = L >> 3;
    const int gj = (bid << 3) + (L & 7);
    float hj = 0.f, bu = 0.f, br = 0.f, bc = 0.f;
    if (w == 15) {
        bu = a.Bu[gl * HID + gj]; br = a.Br[gl * HID + gj]; bc = a.Bc[gl * HID + gj];
    }
    __syncthreads();

    for (int R = 0; R < SEQ + 3; R++) {
        // prefetch layer-0 gate input terms (warp 15, lanes 0-7 are gl=0)
        float zu = 0.f, zr = 0.f, zc = 0.f;
        if (w == 15 && gl == 0 && R < SEQ) {
            zu = __ldg(a.Zu + (size_t)R * HID + gj);
            zr = __ldg(a.Zr + (size_t)R * HID + gj);
            zc = __ldg(a.Zc + (size_t)R * HID + gj);
        }

        // stage: warp l(<4) polls + RAW-copies fp16 row h_l(R-1-l) into SMEM,
        // keeping a register copy (its own 3 chains use it directly)
        uint4 hreg[4];
        if (w < 4) {
            const int l = w;
            char* hb = hbuf_b + l * 2048;
            if (R >= l + 1) {
                int row = R - 1 - l; if (row > SEQ - 1) row = SEQ - 1;
                int tgt = R - l;     if (tgt > SEQ) tgt = SEQ;
                tgt *= 64;
                if (L < NSLOT) {
                    const int* cp = a.ctr + l * (NSLOT * CSTRIDE) + L * CSTRIDE;
                    while (ldacq(cp) < tgt) { }
                }
                __syncwarp();
                const uint4* hr = (const uint4*)(a.H + ((size_t)l * SEQ + row) * HID) + L * 4;
                hreg[0] = ldcg4u(hr + 0);
                hreg[1] = ldcg4u(hr + 1);
                hreg[2] = ldcg4u(hr + 2);
                hreg[3] = ldcg4u(hr + 3);
            } else {
                const uint4 z = make_uint4(0, 0, 0, 0);
                hreg[0] = z; hreg[1] = z; hreg[2] = z; hreg[3] = z;
            }
            *(uint4*)(hb + 0 * 512 + L * 16) = hreg[0];
            *(uint4*)(hb + 1 * 512 + L * 16) = hreg[1];
            *(uint4*)(hb + 2 * 512 + L * 16) = hreg[2];
            *(uint4*)(hb + 3 * 512 + L * 16) = hreg[3];
        }
        __syncthreads();   // bar A

        // majority/self vector in regs
        uint4 hc[4];
        if (w < 4) {
            hc[0] = hreg[0]; hc[1] = hreg[1]; hc[2] = hreg[2]; hc[3] = hreg[3];
        } else {
#pragma unroll
            for (int q = 0; q < 4; q++)
                hc[q] = *(const uint4*)(hbuf_b + vMaj * 2048 + q * 512 + L * 16);
        }

        // chains: dot + 3-shfl partial reduce (R13-proven inline style)
#pragma unroll
        for (int k = 0; k < NCHMAX; k++) {
            const int m = meta[k];
            if (m < 0) continue;
            const int l = m & 3;
            const int t = R - l;
            if (t < 0 || t >= SEQ) continue;
            const int v = (m >> 3) & 3;
            float s = 0.f;
#pragma unroll
            for (int q = 0; q < 4; q++) {
                uint4 hg;
                if (v == vMaj) hg = hc[q];
                else hg = *(const uint4*)(hbuf_b + v * 2048 + q * 512 + L * 16);
                uint4 wg;
                if (k < NREG) wg = wreg[k][q];
                else wg = *(const uint4*)(wrow_b + (size_t)((w - 4) * 7 + (k - NREG)) * 2048 + q * 512 + L * 16);
                s += dot4u(wg, hg);
            }
            s += __shfl_xor_sync(0xffffffffu, s, 16);
            s += __shfl_xor_sync(0xffffffffu, s, 8);
            s += __shfl_xor_sync(0xffffffffu, s, 4);
            if (L < 4) res4[(m >> 5) * 4 + L] = s;
        }
        __syncthreads();   // bar B

        // gates: warp 15, lane = instance
        if (w == 15) {
            const int t = R - gl;
            if (t >= 0 && t < SEQ) {
                const int ibase = (gl * 8 + (L & 7)) * 5;
                const float4 p0 = *(const float4*)(res4 + (ibase + 0) * 4);
                const float4 p1 = *(const float4*)(res4 + (ibase + 1) * 4);
                const float4 p2 = *(const float4*)(res4 + (ibase + 2) * 4);
                const float r0 = (p0.x + p0.y) + (p0.z + p0.w);
                const float r1 = (p1.x + p1.y) + (p1.z + p1.w);
                const float r2 = (p2.x + p2.y) + (p2.z + p2.w);
                float u, r, c;
                if (gl == 0) {
                    u = sigf(r0 + zu + bu);
                    r = sigf(r1 + zr + br);
                    c = sigf(zc + r * r2 + bc);
                } else {
                    const float4 p3 = *(const float4*)(res4 + (ibase + 3) * 4);
                    const float4 p4 = *(const float4*)(res4 + (ibase + 4) * 4);
                    const float s5 = (p3.x + p3.y) + (p3.z + p3.w);
                    const float q5 = (p4.x + p4.y) + (p4.z + p4.w);
                    u = sigf(s5 + r0 + bu);       // shared Uh term feeds u...
                    r = sigf(q5 + r1 + br);
                    c = sigf(s5 + r * r2 + bc);   // ...and c (aliased parameter)
                }
                hj = fmaf(u, hj - c, c);
                stcg_h(a.H + ((size_t)gl * SEQ + t) * HID + gj, __float2half_rn(hj));
                red_release_add(a.ctr + gl * (NSLOT * CSTRIDE) + (bid & (NSLOT - 1)) * CSTRIDE, 1);
                if (t == SEQ - 1) a.out[gl * HID + gj] = hj;
            }
        }
    }
}

// ---------------- launch ----------------
extern "C" void kernel_launch(void* const* d_in, const int* in_sizes, int n_in,
                              void* d_out, int out_size) {
    const float* x   = (const float*)d_in[0];
    const float* Uu  = (const float*)d_in[1];
    const float* Ur  = (const float*)d_in[2];
    const float* U   = (const float*)d_in[3];
    const float* Wu  = (const float*)d_in[4];
    const float* Wr  = (const float*)d_in[5];
    const float* W   = (const float*)d_in[6];
    const float* Bu  = (const float*)d_in[7];
    const float* Br  = (const float*)d_in[8];
    const float* B   = (const float*)d_in[9];
    const float* Uhr = (const float*)d_in[10];
    const float* Uh  = (const float*)d_in[11];
    float* out = (float*)d_out;

    float *Zu, *Zr, *Zc;
    __half* Hh;
    int* ct;
    cudaGetSymbolAddress((void**)&Zu, g_Zu);
    cudaGetSymbolAddress((void**)&Zr, g_Zr);
    cudaGetSymbolAddress((void**)&Zc, g_Zc);
    cudaGetSymbolAddress((void**)&Hh, g_Hh);
    cudaGetSymbolAddress((void**)&ct, g_ctr);

    cudaFuncSetAttribute(quad_scan, cudaFuncAttributeMaxDynamicSharedMemorySize,
                         SMEM_TOTAL_Q);

    reset_ctrs_kernel<<<(4 * NSLOT * CSTRIDE + 255) / 256, 256>>>();

    {   // layer 0 input projections
        dim3 gg(HID / 128, SEQ / 128, 3);
        GemmJob A0{x, Uu, Zu}, B0{x, Ur, Zr}, C0{x, U, Zc};
        sgemm_nt_batch<<<gg, 256>>>(A0, B0, C0);
    }

    QuadArgs q;
    q.Wu = Wu; q.Wr = Wr; q.Wc = W;
    q.Bu = Bu; q.Br = Br; q.Bc = B;
    q.Uh = Uh; q.Uhr = Uhr;
    q.Zu = Zu; q.Zr = Zr; q.Zc = Zc;
    q.H = Hh; q.out = out; q.ctr = ct;
    quad_scan<<<NCTA, 512, SMEM_TOTAL_Q>>>(q);

    (void)in_sizes; (void)n_in; (void)out_size;
}